// round 3
// baseline (speedup 1.0000x reference)
#include <cuda_runtime.h>
#include <cstdint>

#define C 128
#define E_EDGES 1000000
#define TILE 128
#define NTILES ((E_EDGES + TILE - 1) / TILE)
#define BN_EPS 1e-5f

// 512 MB scratch for h1pre (pass1 -> pass2) then h2pre (pass2 -> out), in place.
__device__ float g_h[(size_t)E_EDGES * C];
__device__ __align__(16) float g_sum1[C], g_sq1[C], g_sum2[C], g_sq2[C];
__device__ __align__(16) float g_a1[C], g_c1[C], g_a2[C], g_c2[C];
__device__ int g_is64;

__device__ __forceinline__ unsigned long long pack2(float lo, float hi) {
    unsigned long long r;
    asm("mov.b64 %0, {%1, %2};" : "=l"(r) : "f"(lo), "f"(hi));
    return r;
}
__device__ __forceinline__ void fma2(unsigned long long& c, unsigned long long a,
                                     unsigned long long b) {
    asm("fma.rn.f32x2 %0, %1, %2, %3;" : "=l"(c) : "l"(a), "l"(b), "l"(c));
}
__device__ __forceinline__ float2 unpack2(unsigned long long v) {
    float2 r;
    asm("mov.b64 {%0, %1}, %2;" : "=f"(r.x), "=f"(r.y) : "l"(v));
    return r;
}

__global__ void k_zero(const unsigned* __restrict__ ew) {
    int t = threadIdx.x;
    if (t < C) { g_sum1[t] = 0.f; g_sq1[t] = 0.f; g_sum2[t] = 0.f; g_sq2[t] = 0.f; }
    if (t == 0) {
        // Edge-dtype sniff: int64 edge data (non-negative, < 2^31) has every odd
        // 32-bit word == 0; for int32 data these words are random node indices.
        int all0 = 1;
        #pragma unroll
        for (int k = 0; k < 8; k++) all0 &= (ew[2 * k + 1] == 0u);
        g_is64 = all0;
    }
}

// PASS 1: A = x[i] * x[j] (gather), B = w1, out -> g_h (h1pre), stats -> sum1/sq1
// PASS 2: A = relu(a1*g_h + c1),    B = w2, out -> g_h (h2pre), stats -> sum2/sq2
template <int PASS>
__global__ __launch_bounds__(256) void k_pass(
    const float* __restrict__ x, const void* __restrict__ edges_raw,
    const float* __restrict__ w, const float* __restrict__ bias)
{
    extern __shared__ float smem[];
    float* sW = smem;                       // 128*128 = 16384 floats
    float* sX = smem + 16384;               // 128*132 = 16896 floats (padded tile)
    int*   sI = (int*)(smem + 33280);       // 128
    int*   sJ = (int*)(smem + 33408);       // 128
    float* sScale = smem + 33536;           // 128
    float* sShift = smem + 33664;           // 128 (total 33792 floats)

    const int tid = threadIdx.x;
    const int tx = tid & 15;
    const int ty = tid >> 4;
    const int seg = tid & 31;       // fixed 16B segment (4 floats) owned by this thread
    const int elBase = tid >> 5;    // 0..7
    const int is64 = g_is64;
    const long long* e64 = (const long long*)edges_raw;
    const int*       e32 = (const int*)edges_raw;

    for (int i = tid; i < C * C; i += 256) sW[i] = w[i];
    if (PASS == 2 && tid < C) { sScale[tid] = g_a1[tid]; sShift[tid] = g_c1[tid]; }
    __syncthreads();

    float bch[8];
    #pragma unroll
    for (int q = 0; q < 8; q++) bch[q] = bias[tx * 8 + q];

    float4 sc4 = make_float4(0.f, 0.f, 0.f, 0.f);
    float4 sh4 = make_float4(0.f, 0.f, 0.f, 0.f);
    if (PASS == 2) {
        sc4 = *(const float4*)&sScale[seg * 4];
        sh4 = *(const float4*)&sShift[seg * 4];
    }

    float s1[8], s2[8];
    #pragma unroll
    for (int q = 0; q < 8; q++) { s1[q] = 0.f; s2[q] = 0.f; }

    const float4* x4 = (const float4*)x;

    for (int t = blockIdx.x; t < NTILES; t += gridDim.x) {
        const int e0 = t * TILE;
        if (PASS == 1 && tid < TILE) {
            int e = e0 + tid;
            if (e < E_EDGES) {
                if (is64) {
                    sI[tid] = (int)e64[e];
                    sJ[tid] = (int)e64[(size_t)E_EDGES + e];
                } else {
                    sI[tid] = e32[e];
                    sJ[tid] = e32[(size_t)E_EDGES + e];
                }
            } else {
                sI[tid] = -1;
            }
        }
        if (PASS == 1) __syncthreads();

        // ---- build A tile in SMEM (row = edge, col = k), pitch 132 ----
        if (PASS == 1) {
            #pragma unroll
            for (int el = elBase; el < TILE; el += 8) {
                int ni = sI[el];
                float4 p = make_float4(0.f, 0.f, 0.f, 0.f);
                if (ni >= 0) {
                    float4 a = x4[(size_t)ni * 32 + seg];
                    float4 b = x4[(size_t)sJ[el] * 32 + seg];
                    p = make_float4(a.x * b.x, a.y * b.y, a.z * b.z, a.w * b.w);
                }
                *(float4*)&sX[el * 132 + seg * 4] = p;
            }
        } else {
            #pragma unroll
            for (int el = elBase; el < TILE; el += 8) {
                int e = e0 + el;
                float4 p = make_float4(0.f, 0.f, 0.f, 0.f);
                if (e < E_EDGES) {
                    float4 v = *(const float4*)&g_h[(size_t)e * C + seg * 4];
                    p.x = fmaxf(fmaf(v.x, sc4.x, sh4.x), 0.f);
                    p.y = fmaxf(fmaf(v.y, sc4.y, sh4.y), 0.f);
                    p.z = fmaxf(fmaf(v.z, sc4.z, sh4.z), 0.f);
                    p.w = fmaxf(fmaf(v.w, sc4.w, sh4.w), 0.f);
                }
                *(float4*)&sX[el * 132 + seg * 4] = p;
            }
        }
        __syncthreads();

        // ---- 128x128x128 GEMM, 8x8 per thread, packed f32x2 FMA ----
        unsigned long long acc[8][4];
        #pragma unroll
        for (int i = 0; i < 8; i++)
            #pragma unroll
            for (int j = 0; j < 4; j++) acc[i][j] = 0ull;

        const float* xrow = &sX[(ty * 8) * 132];
        #pragma unroll 2
        for (int k = 0; k < C; k += 2) {
            ulonglong2 b0a = *(const ulonglong2*)&sW[k * C + tx * 8];
            ulonglong2 b0b = *(const ulonglong2*)&sW[k * C + tx * 8 + 4];
            ulonglong2 b1a = *(const ulonglong2*)&sW[(k + 1) * C + tx * 8];
            ulonglong2 b1b = *(const ulonglong2*)&sW[(k + 1) * C + tx * 8 + 4];
            #pragma unroll
            for (int i = 0; i < 8; i++) {
                float2 av = *(const float2*)&xrow[i * 132 + k];
                unsigned long long a0 = pack2(av.x, av.x);
                unsigned long long a1 = pack2(av.y, av.y);
                fma2(acc[i][0], a0, b0a.x);
                fma2(acc[i][1], a0, b0a.y);
                fma2(acc[i][2], a0, b0b.x);
                fma2(acc[i][3], a0, b0b.y);
                fma2(acc[i][0], a1, b1a.x);
                fma2(acc[i][1], a1, b1a.y);
                fma2(acc[i][2], a1, b1b.x);
                fma2(acc[i][3], a1, b1b.y);
            }
        }

        // ---- epilogue: +bias, stats, store to scratch ----
        #pragma unroll
        for (int i = 0; i < 8; i++) {
            int e = e0 + ty * 8 + i;
            if (e >= E_EDGES) break;
            float h[8];
            #pragma unroll
            for (int j = 0; j < 4; j++) {
                float2 u = unpack2(acc[i][j]);
                h[2 * j]     = u.x + bch[2 * j];
                h[2 * j + 1] = u.y + bch[2 * j + 1];
            }
            #pragma unroll
            for (int q = 0; q < 8; q++) { s1[q] += h[q]; s2[q] += h[q] * h[q]; }
            float4* dst = (float4*)&g_h[(size_t)e * C + tx * 8];
            dst[0] = make_float4(h[0], h[1], h[2], h[3]);
            dst[1] = make_float4(h[4], h[5], h[6], h[7]);
        }
        __syncthreads();
    }

    // ---- per-CTA stat reduction (16 partials per channel), one atomic per channel ----
    #pragma unroll
    for (int q = 0; q < 8; q++) sX[ty * C + tx * 8 + q] = s1[q];
    __syncthreads();
    if (tid < C) {
        float tot = 0.f;
        #pragma unroll
        for (int r = 0; r < 16; r++) tot += sX[r * C + tid];
        atomicAdd(PASS == 1 ? &g_sum1[tid] : &g_sum2[tid], tot);
    }
    __syncthreads();
    #pragma unroll
    for (int q = 0; q < 8; q++) sX[ty * C + tx * 8 + q] = s2[q];
    __syncthreads();
    if (tid < C) {
        float tot = 0.f;
        #pragma unroll
        for (int r = 0; r < 16; r++) tot += sX[r * C + tid];
        atomicAdd(PASS == 1 ? &g_sq1[tid] : &g_sq2[tid], tot);
    }
}

__global__ void k_fin(const float* __restrict__ g, const float* __restrict__ be, int which) {
    int c = threadIdx.x;
    float sum = which ? g_sum2[c] : g_sum1[c];
    float sq  = which ? g_sq2[c]  : g_sq1[c];
    float mean = sum * (1.f / E_EDGES);
    float var  = sq * (1.f / E_EDGES) - mean * mean;
    float a = g[c] * rsqrtf(var + BN_EPS);
    float cc = be[c] - mean * a;
    if (which) { g_a2[c] = a; g_c2[c] = cc; }
    else       { g_a1[c] = a; g_c1[c] = cc; }
}

__global__ __launch_bounds__(256) void k_out(const float* __restrict__ wc,
                                             const float* __restrict__ bc,
                                             float* __restrict__ out)
{
    const int lane = threadIdx.x & 31;
    const int warp = threadIdx.x >> 5;
    const int nwarp = gridDim.x * 8;
    const int wg = blockIdx.x * 8 + warp;

    float4 a2 = *(const float4*)&g_a2[lane * 4];
    float4 c2 = *(const float4*)&g_c2[lane * 4];
    float4 wv = *(const float4*)&wc[lane * 4];
    float b = bc[0];

    for (size_t e = wg; e < E_EDGES; e += nwarp) {
        float4 v = *(const float4*)&g_h[e * C + lane * 4];
        float r = fmaxf(fmaf(v.x, a2.x, c2.x), 0.f) * wv.x
                + fmaxf(fmaf(v.y, a2.y, c2.y), 0.f) * wv.y
                + fmaxf(fmaf(v.z, a2.z, c2.z), 0.f) * wv.z
                + fmaxf(fmaf(v.w, a2.w, c2.w), 0.f) * wv.w;
        #pragma unroll
        for (int s = 16; s > 0; s >>= 1) r += __shfl_xor_sync(0xffffffffu, r, s);
        if (lane == 0) out[e] = r + b;
    }
}

extern "C" void kernel_launch(void* const* d_in, const int* in_sizes, int n_in,
                              void* d_out, int out_size) {
    const float* x     = (const float*)d_in[0];
    const void*  edges = d_in[1];
    const float* w1    = (const float*)d_in[2];
    const float* b1    = (const float*)d_in[3];
    const float* g1    = (const float*)d_in[4];
    const float* be1   = (const float*)d_in[5];
    const float* w2    = (const float*)d_in[6];
    const float* b2    = (const float*)d_in[7];
    const float* g2    = (const float*)d_in[8];
    const float* be2   = (const float*)d_in[9];
    const float* wc    = (const float*)d_in[10];
    const float* bc    = (const float*)d_in[11];
    float* out = (float*)d_out;
    (void)in_sizes; (void)n_in; (void)out_size;

    const int smem_bytes = 33792 * 4;  // 132 KB dynamic SMEM
    cudaFuncSetAttribute(k_pass<1>, cudaFuncAttributeMaxDynamicSharedMemorySize, smem_bytes);
    cudaFuncSetAttribute(k_pass<2>, cudaFuncAttributeMaxDynamicSharedMemorySize, smem_bytes);

    k_zero<<<1, 128>>>((const unsigned*)edges);
    k_pass<1><<<148, 256, smem_bytes>>>(x, edges, w1, b1);
    k_fin<<<1, 128>>>(g1, be1, 0);
    k_pass<2><<<148, 256, smem_bytes>>>(x, edges, w2, b2);
    k_fin<<<1, 128>>>(g2, be2, 1);
    k_out<<<2048, 256>>>(wc, bc, out);
}

// round 5
// speedup vs baseline: 1.5559x; 1.5559x over previous
#include <cuda_runtime.h>
#include <cuda_bf16.h>
#include <cstdint>

#define C 128
#define E_EDGES 1000000
#define TILE 128
#define NTILES ((E_EDGES + TILE - 1) / TILE)
#define BN_EPS 1e-5f
#define PITCHB 272   // bytes per bf16 tile row (136 halves: 128 data + 8 pad)

// ---------------- SMEM byte layout (dynamic) ----------------
#define SM_AH    0        // A hi bf16 [128 x 136]   34816 B
#define SM_AL    34816    // A lo bf16               34816 B
#define SM_BH    69632    // B hi bf16 [k=128][n=136]
#define SM_BL    104448   // B lo
#define SM_BIAS  139264   // float[128]
#define SM_SCALE 139776   // float[128]
#define SM_SHIFT 140288   // float[128]
#define SM_I     140800   // int[128]
#define SM_J     141312   // int[128]
#define SM_RED   141824   // float[256]
#define SM_TOTAL 142848
// fp32 stage [128][132] (67584 B) aliases SM_AH/SM_AL after MMA completes.

// 512 MB scratch for h1pre (pass1 -> pass2) then h2pre (pass2 -> out), in place.
__device__ float g_h[(size_t)E_EDGES * C];
__device__ __align__(16) float g_sum1[C], g_sq1[C], g_sum2[C], g_sq2[C];
__device__ __align__(16) float g_a1[C], g_c1[C], g_a2[C], g_c2[C];
__device__ int g_is64;

// ---------------- helpers ----------------
__device__ __forceinline__ uint32_t smem_u32(const void* p) {
    uint32_t a;
    asm("{ .reg .u64 t; cvta.to.shared.u64 t, %1; cvt.u32.u64 %0, t; }" : "=r"(a) : "l"(p));
    return a;
}
__device__ __forceinline__ void ldsm4(uint32_t* r, uint32_t addr) {
    asm volatile("ldmatrix.sync.aligned.m8n8.x4.shared.b16 {%0,%1,%2,%3}, [%4];"
                 : "=r"(r[0]), "=r"(r[1]), "=r"(r[2]), "=r"(r[3]) : "r"(addr));
}
__device__ __forceinline__ void ldsm4t(uint32_t* r, uint32_t addr) {
    asm volatile("ldmatrix.sync.aligned.m8n8.x4.trans.shared.b16 {%0,%1,%2,%3}, [%4];"
                 : "=r"(r[0]), "=r"(r[1]), "=r"(r[2]), "=r"(r[3]) : "r"(addr));
}
__device__ __forceinline__ void mma16816(float* d, const uint32_t* a, const uint32_t* b) {
    asm volatile(
        "mma.sync.aligned.m16n8k16.row.col.f32.bf16.bf16.f32 "
        "{%0,%1,%2,%3}, {%4,%5,%6,%7}, {%8,%9}, {%0,%1,%2,%3};"
        : "+f"(d[0]), "+f"(d[1]), "+f"(d[2]), "+f"(d[3])
        : "r"(a[0]), "r"(a[1]), "r"(a[2]), "r"(a[3]), "r"(b[0]), "r"(b[1]));
}
__device__ __forceinline__ void split_bf16(float v, __nv_bfloat16& h, __nv_bfloat16& l) {
    h = __float2bfloat16_rn(v);
    l = __float2bfloat16_rn(v - __bfloat162float(h));
}
__device__ __forceinline__ uint32_t pack_bf(__nv_bfloat16 a, __nv_bfloat16 b) {
    return ((uint32_t)__bfloat16_as_ushort(b) << 16) | __bfloat16_as_ushort(a);
}

__global__ void k_zero(const unsigned* __restrict__ ew) {
    int t = threadIdx.x;
    if (t < C) { g_sum1[t] = 0.f; g_sq1[t] = 0.f; g_sum2[t] = 0.f; g_sq2[t] = 0.f; }
    if (t == 0) {
        // int64 edge data (non-negative < 2^31) has every odd 32-bit word == 0
        int all0 = 1;
        #pragma unroll
        for (int k = 0; k < 8; k++) all0 &= (ew[2 * k + 1] == 0u);
        g_is64 = all0;
    }
}

// PASS 1: A = x[i]*x[j] (gather), B = w1, D -> h1pre -> g_h, stats1
// PASS 2: A = relu(a1*g_h + c1),  B = w2, D -> h2pre -> g_h, stats2
template <int PASS>
__global__ __launch_bounds__(256) void k_pass_mma(
    const float* __restrict__ x, const void* __restrict__ edges_raw,
    const float* __restrict__ w, const float* __restrict__ bias)
{
    extern __shared__ char sm[];
    const uint32_t sb = smem_u32(sm);
    const int tid = threadIdx.x;
    const int wid = tid >> 5;
    const int lid = tid & 31;
    const int gid = lid >> 2;     // mma group id (row within 8)
    const int tig = lid & 3;      // thread in group (col pair)

    float* sStage = (float*)sm;               // aliases SM_AH/SM_AL
    float* sBias  = (float*)(sm + SM_BIAS);
    float* sScale = (float*)(sm + SM_SCALE);
    float* sShift = (float*)(sm + SM_SHIFT);
    int*   sI     = (int*)(sm + SM_I);
    int*   sJ     = (int*)(sm + SM_J);
    float* sRed   = (float*)(sm + SM_RED);

    if (tid < C) {
        sBias[tid] = bias[tid];
        if (PASS == 2) { sScale[tid] = g_a1[tid]; sShift[tid] = g_c1[tid]; }
    }
    // ---- W -> Bh/Bl, natural [k][n] layout, padded pitch ----
    for (int idx = tid; idx < C * C; idx += 256) {
        int k = idx >> 7, n = idx & 127;
        __nv_bfloat16 hb, lb;
        split_bf16(w[idx], hb, lb);
        uint32_t off = (uint32_t)(k * PITCHB + n * 2);
        *(__nv_bfloat16*)(sm + SM_BH + off) = hb;
        *(__nv_bfloat16*)(sm + SM_BL + off) = lb;
    }
    __syncthreads();

    const int is64 = g_is64;
    const long long* e64 = (const long long*)edges_raw;
    const int*       e32 = (const int*)edges_raw;
    const float4*    x4  = (const float4*)x;

    const int m0  = (wid & 3) * 32;   // warp's 32 rows
    const int n0w = (wid >> 2) * 64;  // warp's 64 cols

    float s1 = 0.f, s2 = 0.f;         // per-thread BN partials (fixed column)
    const int statc  = tid & 127;
    const int statr0 = (tid >> 7) * 64;
    const float statb = sBias[statc];

    const int seg = tid & 31;         // 16B segment for gather
    const int elB = tid >> 5;

    for (int t = blockIdx.x; t < NTILES; t += gridDim.x) {
        const int e0 = t * TILE;
        const int rem = min(TILE, E_EDGES - e0);

        // ================= build A tile (hi/lo bf16, padded pitch) =================
        if (PASS == 1) {
            if (tid < TILE) {
                int e = e0 + tid;
                if (e < E_EDGES) {
                    if (is64) { sI[tid] = (int)e64[e]; sJ[tid] = (int)e64[(size_t)E_EDGES + e]; }
                    else      { sI[tid] = e32[e];      sJ[tid] = e32[(size_t)E_EDGES + e]; }
                } else sI[tid] = -1;
            }
            __syncthreads();
            #pragma unroll
            for (int el = elB; el < TILE; el += 8) {
                int ni = sI[el];
                float4 p = make_float4(0.f, 0.f, 0.f, 0.f);
                if (ni >= 0) {
                    float4 a = x4[(size_t)ni * 32 + seg];
                    float4 b = x4[(size_t)sJ[el] * 32 + seg];
                    p = make_float4(a.x * b.x, a.y * b.y, a.z * b.z, a.w * b.w);
                }
                __nv_bfloat16 h0, h1, h2, h3, l0, l1, l2, l3;
                split_bf16(p.x, h0, l0); split_bf16(p.y, h1, l1);
                split_bf16(p.z, h2, l2); split_bf16(p.w, h3, l3);
                uint32_t off = (uint32_t)(el * PITCHB + seg * 8);
                *(uint2*)(sm + SM_AH + off) = make_uint2(pack_bf(h0, h1), pack_bf(h2, h3));
                *(uint2*)(sm + SM_AL + off) = make_uint2(pack_bf(l0, l1), pack_bf(l2, l3));
            }
        } else {
            #pragma unroll
            for (int i = 0; i < 16; i++) {
                int f = tid + 256 * i;           // float4 index in 128x128 tile
                int row = f >> 5, c4 = f & 31;
                int e = e0 + row;
                float4 p = make_float4(0.f, 0.f, 0.f, 0.f);
                if (e < E_EDGES) {
                    float4 v = *(const float4*)&g_h[(size_t)e * C + c4 * 4];
                    float4 sc = *(const float4*)&sScale[c4 * 4];
                    float4 sh = *(const float4*)&sShift[c4 * 4];
                    p.x = fmaxf(fmaf(v.x, sc.x, sh.x), 0.f);
                    p.y = fmaxf(fmaf(v.y, sc.y, sh.y), 0.f);
                    p.z = fmaxf(fmaf(v.z, sc.z, sh.z), 0.f);
                    p.w = fmaxf(fmaf(v.w, sc.w, sh.w), 0.f);
                }
                __nv_bfloat16 h0, h1, h2, h3, l0, l1, l2, l3;
                split_bf16(p.x, h0, l0); split_bf16(p.y, h1, l1);
                split_bf16(p.z, h2, l2); split_bf16(p.w, h3, l3);
                uint32_t off = (uint32_t)(row * PITCHB + c4 * 8);
                *(uint2*)(sm + SM_AH + off) = make_uint2(pack_bf(h0, h1), pack_bf(h2, h3));
                *(uint2*)(sm + SM_AL + off) = make_uint2(pack_bf(l0, l1), pack_bf(l2, l3));
            }
        }
        __syncthreads();

        // ================= MMA: D = Ah*Bh + Al*Bh + Ah*Bl =================
        float acc[2][8][4];
        #pragma unroll
        for (int mt = 0; mt < 2; mt++)
            #pragma unroll
            for (int nt = 0; nt < 8; nt++)
                #pragma unroll
                for (int q = 0; q < 4; q++) acc[mt][nt][q] = 0.f;

        #pragma unroll
        for (int ks = 0; ks < 8; ks++) {
            uint32_t ah[2][4], al[2][4];
            {
                uint32_t off = (uint32_t)((m0 + (lid & 15)) * PITCHB
                                          + (ks * 16 + (lid >> 4) * 8) * 2);
                ldsm4(ah[0], sb + SM_AH + off);
                ldsm4(ah[1], sb + SM_AH + off + 16 * PITCHB);
                ldsm4(al[0], sb + SM_AL + off);
                ldsm4(al[1], sb + SM_AL + off + 16 * PITCHB);
            }
            #pragma unroll
            for (int p = 0; p < 4; p++) {
                uint32_t boff = (uint32_t)(
                    (ks * 16 + (lid & 7) + ((lid >> 3) & 1) * 8) * PITCHB
                    + (n0w + p * 16 + (lid >> 4) * 8) * 2);
                uint32_t bh[4], bl[4];
                ldsm4t(bh, sb + SM_BH + boff);
                ldsm4t(bl, sb + SM_BL + boff);
                #pragma unroll
                for (int mt = 0; mt < 2; mt++) {
                    mma16816(acc[mt][2 * p],     ah[mt], bh);
                    mma16816(acc[mt][2 * p],     al[mt], bh);
                    mma16816(acc[mt][2 * p],     ah[mt], bl);
                    mma16816(acc[mt][2 * p + 1], ah[mt], bh + 2);
                    mma16816(acc[mt][2 * p + 1], al[mt], bh + 2);
                    mma16816(acc[mt][2 * p + 1], ah[mt], bl + 2);
                }
            }
        }
        __syncthreads();   // all warps done reading A before stage aliases it

        // ================= epilogue: acc (+bias) -> fp32 stage =================
        #pragma unroll
        for (int mt = 0; mt < 2; mt++) {
            int r0 = m0 + mt * 16 + gid;
            #pragma unroll
            for (int nt = 0; nt < 8; nt++) {
                int cb = n0w + nt * 8 + 2 * tig;
                float2 bb = *(const float2*)&sBias[cb];
                *(float2*)&sStage[r0 * 132 + cb] =
                    make_float2(acc[mt][nt][0] + bb.x, acc[mt][nt][1] + bb.y);
                *(float2*)&sStage[(r0 + 8) * 132 + cb] =
                    make_float2(acc[mt][nt][2] + bb.x, acc[mt][nt][3] + bb.y);
            }
        }
        __syncthreads();

        // ---- coalesced store to scratch ----
        #pragma unroll
        for (int i = 0; i < 16; i++) {
            int f = tid + 256 * i;
            int row = f >> 5, c4 = f & 31;
            int e = e0 + row;
            if (e < E_EDGES)
                *(float4*)&g_h[(size_t)e * C + c4 * 4] = *(float4*)&sStage[row * 132 + c4 * 4];
        }
        // ---- per-column stats (thread owns fixed column) ----
        if (rem == TILE) {
            #pragma unroll 8
            for (int r = statr0; r < statr0 + 64; r++) {
                float v = sStage[r * 132 + statc];
                s1 += v; s2 += v * v;
            }
        } else {
            for (int r = statr0; r < statr0 + 64; r++) {
                if (r < rem) {
                    float v = sStage[r * 132 + statc];
                    s1 += v; s2 += v * v;
                }
            }
        }
        __syncthreads();
    }
    (void)statb;

    // ---- combine stats: 2 partials per column -> one atomic each ----
    sRed[tid] = s1;
    __syncthreads();
    if (tid < C)
        atomicAdd((PASS == 1 ? g_sum1 : g_sum2) + tid, sRed[tid] + sRed[tid + 128]);
    __syncthreads();
    sRed[tid] = s2;
    __syncthreads();
    if (tid < C)
        atomicAdd((PASS == 1 ? g_sq1 : g_sq2) + tid, sRed[tid] + sRed[tid + 128]);
}

__global__ void k_fin(const float* __restrict__ g, const float* __restrict__ be, int which) {
    int c = threadIdx.x;
    float sum = which ? g_sum2[c] : g_sum1[c];
    float sq  = which ? g_sq2[c]  : g_sq1[c];
    float mean = sum * (1.f / E_EDGES);
    float var  = sq * (1.f / E_EDGES) - mean * mean;
    float a = g[c] * rsqrtf(var + BN_EPS);
    float cc = be[c] - mean * a;
    if (which) { g_a2[c] = a; g_c2[c] = cc; }
    else       { g_a1[c] = a; g_c1[c] = cc; }
}

__global__ __launch_bounds__(256) void k_out(const float* __restrict__ wc,
                                             const float* __restrict__ bc,
                                             float* __restrict__ out)
{
    const int lane = threadIdx.x & 31;
    const int warp = threadIdx.x >> 5;
    const int nwarp = gridDim.x * 8;
    const int wg = blockIdx.x * 8 + warp;

    float4 a2 = *(const float4*)&g_a2[lane * 4];
    float4 c2 = *(const float4*)&g_c2[lane * 4];
    float4 wv = *(const float4*)&wc[lane * 4];
    float b = bc[0];

    for (size_t e = wg; e < E_EDGES; e += nwarp) {
        float4 v = *(const float4*)&g_h[e * C + lane * 4];
        float r = fmaxf(fmaf(v.x, a2.x, c2.x), 0.f) * wv.x
                + fmaxf(fmaf(v.y, a2.y, c2.y), 0.f) * wv.y
                + fmaxf(fmaf(v.z, a2.z, c2.z), 0.f) * wv.z
                + fmaxf(fmaf(v.w, a2.w, c2.w), 0.f) * wv.w;
        #pragma unroll
        for (int s = 16; s > 0; s >>= 1) r += __shfl_xor_sync(0xffffffffu, r, s);
        if (lane == 0) out[e] = r + b;
    }
}

extern "C" void kernel_launch(void* const* d_in, const int* in_sizes, int n_in,
                              void* d_out, int out_size) {
    const float* x     = (const float*)d_in[0];
    const void*  edges = d_in[1];
    const float* w1    = (const float*)d_in[2];
    const float* b1    = (const float*)d_in[3];
    const float* g1    = (const float*)d_in[4];
    const float* be1   = (const float*)d_in[5];
    const float* w2    = (const float*)d_in[6];
    const float* b2    = (const float*)d_in[7];
    const float* g2    = (const float*)d_in[8];
    const float* be2   = (const float*)d_in[9];
    const float* wc    = (const float*)d_in[10];
    const float* bc    = (const float*)d_in[11];
    float* out = (float*)d_out;
    (void)in_sizes; (void)n_in; (void)out_size;

    cudaFuncSetAttribute(k_pass_mma<1>, cudaFuncAttributeMaxDynamicSharedMemorySize, SM_TOTAL);
    cudaFuncSetAttribute(k_pass_mma<2>, cudaFuncAttributeMaxDynamicSharedMemorySize, SM_TOTAL);

    k_zero<<<1, 128>>>((const unsigned*)edges);
    k_pass_mma<1><<<148, 256, SM_TOTAL>>>(x, edges, w1, b1);
    k_fin<<<1, 128>>>(g1, be1, 0);
    k_pass_mma<2><<<148, 256, SM_TOTAL>>>(x, edges, w2, b2);
    k_fin<<<1, 128>>>(g2, be2, 1);
    k_out<<<2048, 256>>>(wc, bc, out);
}

// round 6
// speedup vs baseline: 2.1109x; 1.3567x over previous
#include <cuda_runtime.h>
#include <cuda_bf16.h>
#include <cstdint>

#define C 128
#define E_EDGES 1000000
#define TILE 64
#define NTILES (E_EDGES / TILE)   // 15625 exact, no remainder
#define BN_EPS 1e-5f
#define PITCHB 272   // bytes per bf16 tile row (136 halves: 128 data + 8 pad)

// ---------------- SMEM byte layout (dynamic), TILE=64 ----------------
#define SM_AH    0        // A hi bf16 [64 x 136]    17408 B
#define SM_AL    17408    // A lo bf16               17408 B
#define SM_BH    34816    // B hi bf16 [k=128][n=136] 34816 B
#define SM_BL    69632    // B lo                     34816 B
#define SM_BIAS  104448   // float[128]
#define SM_SCALE 104960   // float[128]
#define SM_SHIFT 105472   // float[128]
#define SM_I     105984   // int[64]
#define SM_J     106240   // int[64]
#define SM_RED   106496   // float[256]
#define SM_TOTAL 107520
// fp32 stage [64][132] (33792 B) aliases SM_AH/SM_AL after MMA completes.

// 512 MB scratch for h1pre (pass1 -> pass2) then h2pre (pass2 -> out), in place.
__device__ float g_h[(size_t)E_EDGES * C];
__device__ __align__(16) float g_sum1[C], g_sq1[C], g_sum2[C], g_sq2[C];
__device__ __align__(16) float g_a1[C], g_c1[C], g_a2[C], g_c2[C];
__device__ int g_is64;

// ---------------- helpers ----------------
__device__ __forceinline__ uint32_t smem_u32(const void* p) {
    uint32_t a;
    asm("{ .reg .u64 t; cvta.to.shared.u64 t, %1; cvt.u32.u64 %0, t; }" : "=r"(a) : "l"(p));
    return a;
}
__device__ __forceinline__ void ldsm4(uint32_t* r, uint32_t addr) {
    asm volatile("ldmatrix.sync.aligned.m8n8.x4.shared.b16 {%0,%1,%2,%3}, [%4];"
                 : "=r"(r[0]), "=r"(r[1]), "=r"(r[2]), "=r"(r[3]) : "r"(addr));
}
__device__ __forceinline__ void ldsm4t(uint32_t* r, uint32_t addr) {
    asm volatile("ldmatrix.sync.aligned.m8n8.x4.trans.shared.b16 {%0,%1,%2,%3}, [%4];"
                 : "=r"(r[0]), "=r"(r[1]), "=r"(r[2]), "=r"(r[3]) : "r"(addr));
}
__device__ __forceinline__ void mma16816(float* d, const uint32_t* a, const uint32_t* b) {
    asm volatile(
        "mma.sync.aligned.m16n8k16.row.col.f32.bf16.bf16.f32 "
        "{%0,%1,%2,%3}, {%4,%5,%6,%7}, {%8,%9}, {%0,%1,%2,%3};"
        : "+f"(d[0]), "+f"(d[1]), "+f"(d[2]), "+f"(d[3])
        : "r"(a[0]), "r"(a[1]), "r"(a[2]), "r"(a[3]), "r"(b[0]), "r"(b[1]));
}
__device__ __forceinline__ void split_bf16(float v, __nv_bfloat16& h, __nv_bfloat16& l) {
    h = __float2bfloat16_rn(v);
    l = __float2bfloat16_rn(v - __bfloat162float(h));
}
__device__ __forceinline__ uint32_t pack_bf(__nv_bfloat16 a, __nv_bfloat16 b) {
    return ((uint32_t)__bfloat16_as_ushort(b) << 16) | __bfloat16_as_ushort(a);
}

__global__ void k_zero(const unsigned* __restrict__ ew) {
    int t = threadIdx.x;
    if (t < C) { g_sum1[t] = 0.f; g_sq1[t] = 0.f; g_sum2[t] = 0.f; g_sq2[t] = 0.f; }
    if (t == 0) {
        // int64 edge data (non-negative < 2^31) has every odd 32-bit word == 0
        int all0 = 1;
        #pragma unroll
        for (int k = 0; k < 8; k++) all0 &= (ew[2 * k + 1] == 0u);
        g_is64 = all0;
    }
}

// PASS 1: A = x[i]*x[j] (gather), B = w1, D -> h1pre -> g_h, stats1
// PASS 2: A = relu(a1*g_h + c1),  B = w2, D -> h2pre -> g_h, stats2
template <int PASS>
__global__ __launch_bounds__(256, 2) void k_pass_mma(
    const float* __restrict__ x, const void* __restrict__ edges_raw,
    const float* __restrict__ w, const float* __restrict__ bias)
{
    extern __shared__ char sm[];
    const uint32_t sb = smem_u32(sm);
    const int tid = threadIdx.x;
    const int wid = tid >> 5;
    const int lid = tid & 31;
    const int gid = lid >> 2;     // mma group id (row within 8)
    const int tig = lid & 3;      // thread in group (col pair)

    float* sStage = (float*)sm;               // aliases SM_AH/SM_AL
    float* sBias  = (float*)(sm + SM_BIAS);
    float* sScale = (float*)(sm + SM_SCALE);
    float* sShift = (float*)(sm + SM_SHIFT);
    int*   sI     = (int*)(sm + SM_I);
    int*   sJ     = (int*)(sm + SM_J);
    float* sRed   = (float*)(sm + SM_RED);

    if (tid < C) {
        sBias[tid] = bias[tid];
        if (PASS == 2) { sScale[tid] = g_a1[tid]; sShift[tid] = g_c1[tid]; }
    }
    // ---- W -> Bh/Bl, natural [k][n] layout, padded pitch ----
    for (int idx = tid; idx < C * C; idx += 256) {
        int k = idx >> 7, n = idx & 127;
        __nv_bfloat16 hb, lb;
        split_bf16(w[idx], hb, lb);
        uint32_t off = (uint32_t)(k * PITCHB + n * 2);
        *(__nv_bfloat16*)(sm + SM_BH + off) = hb;
        *(__nv_bfloat16*)(sm + SM_BL + off) = lb;
    }
    __syncthreads();

    const int is64 = g_is64;
    const long long* e64 = (const long long*)edges_raw;
    const int*       e32 = (const int*)edges_raw;
    const float4*    x4  = (const float4*)x;

    const int m0  = (wid & 3) * 16;   // warp's 16 rows
    const int n0w = (wid >> 2) * 64;  // warp's 64 cols

    float s1 = 0.f, s2 = 0.f;         // per-thread BN partials (fixed column)
    const int statc  = tid & 127;
    const int statr0 = (tid >> 7) * 32;

    const int seg = tid & 31;         // 16B segment for gather
    const int elB = tid >> 5;

    for (int t = blockIdx.x; t < NTILES; t += gridDim.x) {
        const int e0 = t * TILE;

        // ================= build A tile (hi/lo bf16, padded pitch) =================
        if (PASS == 1) {
            if (tid < TILE) {
                int e = e0 + tid;
                if (is64) { sI[tid] = (int)e64[e]; sJ[tid] = (int)e64[(size_t)E_EDGES + e]; }
                else      { sI[tid] = e32[e];      sJ[tid] = e32[(size_t)E_EDGES + e]; }
            }
            __syncthreads();
            #pragma unroll
            for (int el = elB; el < TILE; el += 8) {
                float4 a = x4[(size_t)sI[el] * 32 + seg];
                float4 b = x4[(size_t)sJ[el] * 32 + seg];
                float4 p = make_float4(a.x * b.x, a.y * b.y, a.z * b.z, a.w * b.w);
                __nv_bfloat16 h0, h1, h2, h3, l0, l1, l2, l3;
                split_bf16(p.x, h0, l0); split_bf16(p.y, h1, l1);
                split_bf16(p.z, h2, l2); split_bf16(p.w, h3, l3);
                uint32_t off = (uint32_t)(el * PITCHB + seg * 8);
                *(uint2*)(sm + SM_AH + off) = make_uint2(pack_bf(h0, h1), pack_bf(h2, h3));
                *(uint2*)(sm + SM_AL + off) = make_uint2(pack_bf(l0, l1), pack_bf(l2, l3));
            }
        } else {
            #pragma unroll
            for (int i = 0; i < 8; i++) {
                int f = tid + 256 * i;           // float4 index in 64x128 tile
                int row = f >> 5, c4 = f & 31;
                float4 v = *(const float4*)&g_h[(size_t)(e0 + row) * C + c4 * 4];
                float4 sc = *(const float4*)&sScale[c4 * 4];
                float4 sh = *(const float4*)&sShift[c4 * 4];
                float4 p;
                p.x = fmaxf(fmaf(v.x, sc.x, sh.x), 0.f);
                p.y = fmaxf(fmaf(v.y, sc.y, sh.y), 0.f);
                p.z = fmaxf(fmaf(v.z, sc.z, sh.z), 0.f);
                p.w = fmaxf(fmaf(v.w, sc.w, sh.w), 0.f);
                __nv_bfloat16 h0, h1, h2, h3, l0, l1, l2, l3;
                split_bf16(p.x, h0, l0); split_bf16(p.y, h1, l1);
                split_bf16(p.z, h2, l2); split_bf16(p.w, h3, l3);
                uint32_t off = (uint32_t)(row * PITCHB + c4 * 8);
                *(uint2*)(sm + SM_AH + off) = make_uint2(pack_bf(h0, h1), pack_bf(h2, h3));
                *(uint2*)(sm + SM_AL + off) = make_uint2(pack_bf(l0, l1), pack_bf(l2, l3));
            }
        }
        __syncthreads();

        // ================= MMA: D = Ah*Bh + Al*Bh + Ah*Bl =================
        float acc[8][4];
        #pragma unroll
        for (int nt = 0; nt < 8; nt++)
            #pragma unroll
            for (int q = 0; q < 4; q++) acc[nt][q] = 0.f;

        #pragma unroll
        for (int ks = 0; ks < 8; ks++) {
            uint32_t ah[4], al[4];
            {
                uint32_t off = (uint32_t)((m0 + (lid & 15)) * PITCHB
                                          + (ks * 16 + (lid >> 4) * 8) * 2);
                ldsm4(ah, sb + SM_AH + off);
                ldsm4(al, sb + SM_AL + off);
            }
            #pragma unroll
            for (int p = 0; p < 4; p++) {
                uint32_t boff = (uint32_t)(
                    (ks * 16 + (lid & 7) + ((lid >> 3) & 1) * 8) * PITCHB
                    + (n0w + p * 16 + (lid >> 4) * 8) * 2);
                uint32_t bh[4], bl[4];
                ldsm4t(bh, sb + SM_BH + boff);
                ldsm4t(bl, sb + SM_BL + boff);
                mma16816(acc[2 * p],     ah, bh);
                mma16816(acc[2 * p],     al, bh);
                mma16816(acc[2 * p],     ah, bl);
                mma16816(acc[2 * p + 1], ah, bh + 2);
                mma16816(acc[2 * p + 1], al, bh + 2);
                mma16816(acc[2 * p + 1], ah, bl + 2);
            }
        }
        __syncthreads();   // all warps done reading A before stage aliases it

        // ================= epilogue: acc (+bias) -> fp32 stage =================
        {
            int r0 = m0 + gid;
            #pragma unroll
            for (int nt = 0; nt < 8; nt++) {
                int cb = n0w + nt * 8 + 2 * tig;
                float2 bb = *(const float2*)&sBias[cb];
                *(float2*)&sStage[r0 * 132 + cb] =
                    make_float2(acc[nt][0] + bb.x, acc[nt][1] + bb.y);
                *(float2*)&sStage[(r0 + 8) * 132 + cb] =
                    make_float2(acc[nt][2] + bb.x, acc[nt][3] + bb.y);
            }
        }
        __syncthreads();

        // ---- coalesced store to scratch ----
        #pragma unroll
        for (int i = 0; i < 8; i++) {
            int f = tid + 256 * i;
            int row = f >> 5, c4 = f & 31;
            *(float4*)&g_h[(size_t)(e0 + row) * C + c4 * 4] = *(float4*)&sStage[row * 132 + c4 * 4];
        }
        // ---- per-column stats (thread owns fixed column) ----
        #pragma unroll 8
        for (int r = statr0; r < statr0 + 32; r++) {
            float v = sStage[r * 132 + statc];
            s1 += v; s2 += v * v;
        }
        __syncthreads();
    }

    // ---- combine stats: 2 partials per column -> one atomic each ----
    sRed[tid] = s1;
    __syncthreads();
    if (tid < C)
        atomicAdd((PASS == 1 ? g_sum1 : g_sum2) + tid, sRed[tid] + sRed[tid + 128]);
    __syncthreads();
    sRed[tid] = s2;
    __syncthreads();
    if (tid < C)
        atomicAdd((PASS == 1 ? g_sq1 : g_sq2) + tid, sRed[tid] + sRed[tid + 128]);
}

__global__ void k_fin(const float* __restrict__ g, const float* __restrict__ be, int which) {
    int c = threadIdx.x;
    float sum = which ? g_sum2[c] : g_sum1[c];
    float sq  = which ? g_sq2[c]  : g_sq1[c];
    float mean = sum * (1.f / E_EDGES);
    float var  = sq * (1.f / E_EDGES) - mean * mean;
    float a = g[c] * rsqrtf(var + BN_EPS);
    float cc = be[c] - mean * a;
    if (which) { g_a2[c] = a; g_c2[c] = cc; }
    else       { g_a1[c] = a; g_c1[c] = cc; }
}

__global__ __launch_bounds__(256) void k_out(const float* __restrict__ wc,
                                             const float* __restrict__ bc,
                                             float* __restrict__ out)
{
    const int lane = threadIdx.x & 31;
    const int warp = threadIdx.x >> 5;
    const int nwarp = gridDim.x * 8;
    const int wg = blockIdx.x * 8 + warp;

    float4 a2 = *(const float4*)&g_a2[lane * 4];
    float4 c2 = *(const float4*)&g_c2[lane * 4];
    float4 wv = *(const float4*)&wc[lane * 4];
    float b = bc[0];

    for (size_t e = wg; e < E_EDGES; e += nwarp) {
        float4 v = *(const float4*)&g_h[e * C + lane * 4];
        float r = fmaxf(fmaf(v.x, a2.x, c2.x), 0.f) * wv.x
                + fmaxf(fmaf(v.y, a2.y, c2.y), 0.f) * wv.y
                + fmaxf(fmaf(v.z, a2.z, c2.z), 0.f) * wv.z
                + fmaxf(fmaf(v.w, a2.w, c2.w), 0.f) * wv.w;
        #pragma unroll
        for (int s = 16; s > 0; s >>= 1) r += __shfl_xor_sync(0xffffffffu, r, s);
        if (lane == 0) out[e] = r + b;
    }
}

extern "C" void kernel_launch(void* const* d_in, const int* in_sizes, int n_in,
                              void* d_out, int out_size) {
    const float* x     = (const float*)d_in[0];
    const void*  edges = d_in[1];
    const float* w1    = (const float*)d_in[2];
    const float* b1    = (const float*)d_in[3];
    const float* g1    = (const float*)d_in[4];
    const float* be1   = (const float*)d_in[5];
    const float* w2    = (const float*)d_in[6];
    const float* b2    = (const float*)d_in[7];
    const float* g2    = (const float*)d_in[8];
    const float* be2   = (const float*)d_in[9];
    const float* wc    = (const float*)d_in[10];
    const float* bc    = (const float*)d_in[11];
    float* out = (float*)d_out;
    (void)in_sizes; (void)n_in; (void)out_size;

    cudaFuncSetAttribute(k_pass_mma<1>, cudaFuncAttributeMaxDynamicSharedMemorySize, SM_TOTAL);
    cudaFuncSetAttribute(k_pass_mma<2>, cudaFuncAttributeMaxDynamicSharedMemorySize, SM_TOTAL);

    k_zero<<<1, 128>>>((const unsigned*)edges);
    k_pass_mma<1><<<296, 256, SM_TOTAL>>>(x, edges, w1, b1);
    k_fin<<<1, 128>>>(g1, be1, 0);
    k_pass_mma<2><<<296, 256, SM_TOTAL>>>(x, edges, w2, b2);
    k_fin<<<1, 128>>>(g2, be2, 1);
    k_out<<<2048, 256>>>(wc, bc, out);
}

// round 7
// speedup vs baseline: 2.6510x; 1.2559x over previous
#include <cuda_runtime.h>
#include <cuda_bf16.h>
#include <cstdint>

#define C 128
#define E_EDGES 1000000
#define TILE 64
#define NTILES (E_EDGES / TILE)   // 15625 exact
#define BN_EPS 1e-5f
#define PITCHB 272   // bytes per bf16 tile row (136 halves: 128 data + 8 pad)

// ---------------- SMEM byte layout (dynamic), TILE=64 ----------------
#define SM_AH    0        // A hi bf16 [64 x 136]     17408 B
#define SM_AL    17408    // A lo bf16                17408 B
#define SM_BH    34816    // B hi bf16 [k=128][n=136] 34816 B
#define SM_BL    69632    // B lo                     34816 B
#define SM_BIAS  104448   // float[128]
#define SM_SCALE 104960   // float[128]
#define SM_SHIFT 105472   // float[128]
#define SM_I     105984   // int[2][64] double-buffered
#define SM_J     106496   // int[2][64]
#define SM_RED1  107008   // float[128]
#define SM_RED2  107520   // float[128]
#define SM_TOTAL 108032

// 512 MB scratch for h1pre (pass1 -> pass2) then h2pre (pass2 -> out), in place.
__device__ float g_h[(size_t)E_EDGES * C];
__device__ __align__(16) float g_sum1[C], g_sq1[C], g_sum2[C], g_sq2[C];
__device__ __align__(16) float g_a1[C], g_c1[C], g_a2[C], g_c2[C];
__device__ int g_is64;

// ---------------- helpers ----------------
__device__ __forceinline__ uint32_t smem_u32(const void* p) {
    uint32_t a;
    asm("{ .reg .u64 t; cvta.to.shared.u64 t, %1; cvt.u32.u64 %0, t; }" : "=r"(a) : "l"(p));
    return a;
}
__device__ __forceinline__ void ldsm4(uint32_t* r, uint32_t addr) {
    asm volatile("ldmatrix.sync.aligned.m8n8.x4.shared.b16 {%0,%1,%2,%3}, [%4];"
                 : "=r"(r[0]), "=r"(r[1]), "=r"(r[2]), "=r"(r[3]) : "r"(addr));
}
__device__ __forceinline__ void ldsm4t(uint32_t* r, uint32_t addr) {
    asm volatile("ldmatrix.sync.aligned.m8n8.x4.trans.shared.b16 {%0,%1,%2,%3}, [%4];"
                 : "=r"(r[0]), "=r"(r[1]), "=r"(r[2]), "=r"(r[3]) : "r"(addr));
}
__device__ __forceinline__ void mma16816(float* d, const uint32_t* a, const uint32_t* b) {
    asm volatile(
        "mma.sync.aligned.m16n8k16.row.col.f32.bf16.bf16.f32 "
        "{%0,%1,%2,%3}, {%4,%5,%6,%7}, {%8,%9}, {%0,%1,%2,%3};"
        : "+f"(d[0]), "+f"(d[1]), "+f"(d[2]), "+f"(d[3])
        : "r"(a[0]), "r"(a[1]), "r"(a[2]), "r"(a[3]), "r"(b[0]), "r"(b[1]));
}
__device__ __forceinline__ void split_bf16(float v, __nv_bfloat16& h, __nv_bfloat16& l) {
    h = __float2bfloat16_rn(v);
    l = __float2bfloat16_rn(v - __bfloat162float(h));
}
__device__ __forceinline__ uint32_t pack_bf(__nv_bfloat16 a, __nv_bfloat16 b) {
    return ((uint32_t)__bfloat16_as_ushort(b) << 16) | __bfloat16_as_ushort(a);
}

__global__ void k_zero(const unsigned* __restrict__ ew) {
    int t = threadIdx.x;
    if (t < C) { g_sum1[t] = 0.f; g_sq1[t] = 0.f; g_sum2[t] = 0.f; g_sq2[t] = 0.f; }
    if (t == 0) {
        // int64 edge data (non-negative < 2^31) has every odd 32-bit word == 0
        int all0 = 1;
        #pragma unroll
        for (int k = 0; k < 8; k++) all0 &= (ew[2 * k + 1] == 0u);
        g_is64 = all0;
    }
}

// PASS 1: A = x[i]*x[j] (gather), B = w1, D -> h1pre -> g_h, stats1
// PASS 2: A = relu(a1*g_h + c1),  B = w2, D -> h2pre -> g_h, stats2
template <int PASS>
__global__ __launch_bounds__(256, 2) void k_pass_mma(
    const float* __restrict__ x, const void* __restrict__ edges_raw,
    const float* __restrict__ w, const float* __restrict__ bias)
{
    extern __shared__ char sm[];
    const uint32_t sb = smem_u32(sm);
    const int tid = threadIdx.x;
    const int wid = tid >> 5;
    const int lid = tid & 31;
    const int gid = lid >> 2;
    const int tig = lid & 3;
    const int m0 = (wid & 1) * 32;    // warp's 32 rows
    const int n0 = (wid >> 1) * 32;   // warp's 32 cols

    float* sBias  = (float*)(sm + SM_BIAS);
    float* sScale = (float*)(sm + SM_SCALE);
    float* sShift = (float*)(sm + SM_SHIFT);
    int*   sI     = (int*)(sm + SM_I);
    int*   sJ     = (int*)(sm + SM_J);
    float* sRed1  = (float*)(sm + SM_RED1);
    float* sRed2  = (float*)(sm + SM_RED2);

    if (tid < C) {
        sBias[tid] = bias[tid];
        sRed1[tid] = 0.f; sRed2[tid] = 0.f;
        if (PASS == 2) { sScale[tid] = g_a1[tid]; sShift[tid] = g_c1[tid]; }
    }
    // ---- W -> Bh/Bl, natural [k][n] layout, padded pitch ----
    for (int idx = tid; idx < C * C; idx += 256) {
        int k = idx >> 7, n = idx & 127;
        __nv_bfloat16 hb, lb;
        split_bf16(w[idx], hb, lb);
        uint32_t off = (uint32_t)(k * PITCHB + n * 2);
        *(__nv_bfloat16*)(sm + SM_BH + off) = hb;
        *(__nv_bfloat16*)(sm + SM_BL + off) = lb;
    }
    __syncthreads();

    const int is64 = g_is64;
    const long long* e64 = (const long long*)edges_raw;
    const int*       e32 = (const int*)edges_raw;
    const float4*    x4  = (const float4*)x;

    const int rowb = tid >> 5;    // row base 0..7 (rows rowb + 8i)
    const int cseg = tid & 31;    // float4 column group

    float4 sc4 = make_float4(0.f,0.f,0.f,0.f), sh4 = sc4;
    if (PASS == 2) {
        sc4 = *(const float4*)&sScale[cseg * 4];
        sh4 = *(const float4*)&sShift[cseg * 4];
    }

    float2 s1v[4], s2v[4];
    #pragma unroll
    for (int q = 0; q < 4; q++) { s1v[q] = make_float2(0.f,0.f); s2v[q] = make_float2(0.f,0.f); }

    // ---- prologue: prefetch tile t0 into registers ----
    float4 p[8];
    int buf = 0;
    const int t0 = blockIdx.x;
    if (PASS == 1) {
        if (t0 < NTILES && tid < TILE) {
            int e = t0 * TILE + tid;
            if (is64) { sI[tid] = (int)e64[e]; sJ[tid] = (int)e64[(size_t)E_EDGES + e]; }
            else      { sI[tid] = e32[e];      sJ[tid] = e32[(size_t)E_EDGES + e]; }
        }
        __syncthreads();
        if (t0 < NTILES) {
            #pragma unroll
            for (int i = 0; i < 8; i++) {
                int el = rowb + 8 * i;
                float4 a = x4[(size_t)sI[el] * 32 + cseg];
                float4 b = x4[(size_t)sJ[el] * 32 + cseg];
                p[i] = make_float4(a.x*b.x, a.y*b.y, a.z*b.z, a.w*b.w);
            }
        }
    } else {
        if (t0 < NTILES) {
            #pragma unroll
            for (int i = 0; i < 8; i++)
                p[i] = *(const float4*)&g_h[(size_t)(t0 * TILE + rowb + 8 * i) * C + cseg * 4];
        }
    }

    for (int t = t0; t < NTILES; t += gridDim.x) {
        const int e0 = t * TILE;
        const int tn = t + gridDim.x;
        const int nbuf = buf ^ 1;

        // ---- write A tile (hi/lo bf16) from prefetched regs ----
        #pragma unroll
        for (int i = 0; i < 8; i++) {
            float4 v = p[i];
            if (PASS == 2) {
                v.x = fmaxf(fmaf(v.x, sc4.x, sh4.x), 0.f);
                v.y = fmaxf(fmaf(v.y, sc4.y, sh4.y), 0.f);
                v.z = fmaxf(fmaf(v.z, sc4.z, sh4.z), 0.f);
                v.w = fmaxf(fmaf(v.w, sc4.w, sh4.w), 0.f);
            }
            __nv_bfloat16 h0,h1,h2,h3,l0,l1,l2,l3;
            split_bf16(v.x,h0,l0); split_bf16(v.y,h1,l1);
            split_bf16(v.z,h2,l2); split_bf16(v.w,h3,l3);
            uint32_t off = (uint32_t)((rowb + 8*i) * PITCHB + cseg * 8);
            *(uint2*)(sm + SM_AH + off) = make_uint2(pack_bf(h0,h1), pack_bf(h2,h3));
            *(uint2*)(sm + SM_AL + off) = make_uint2(pack_bf(l0,l1), pack_bf(l2,l3));
        }
        // ---- stage next tile's edge indices (pass 1) ----
        if (PASS == 1 && tn < NTILES && tid < TILE) {
            int e = tn * TILE + tid;
            if (is64) { sI[nbuf*64+tid] = (int)e64[e]; sJ[nbuf*64+tid] = (int)e64[(size_t)E_EDGES + e]; }
            else      { sI[nbuf*64+tid] = e32[e];      sJ[nbuf*64+tid] = e32[(size_t)E_EDGES + e]; }
        }
        __syncthreads();

        // ---- prefetch next tile's A data (overlaps with MMA below) ----
        if (tn < NTILES) {
            if (PASS == 1) {
                #pragma unroll
                for (int i = 0; i < 8; i++) {
                    int el = rowb + 8 * i;
                    float4 a = x4[(size_t)sI[nbuf*64+el] * 32 + cseg];
                    float4 b = x4[(size_t)sJ[nbuf*64+el] * 32 + cseg];
                    p[i] = make_float4(a.x*b.x, a.y*b.y, a.z*b.z, a.w*b.w);
                }
            } else {
                #pragma unroll
                for (int i = 0; i < 8; i++)
                    p[i] = *(const float4*)&g_h[(size_t)(tn*TILE + rowb + 8*i) * C + cseg * 4];
            }
        }

        // ---- MMA: D = Ah*Bh + Al*Bh + Ah*Bl (32x32 warp tile) ----
        float acc[2][4][4];
        #pragma unroll
        for (int mt = 0; mt < 2; mt++)
            #pragma unroll
            for (int q = 0; q < 4; q++)
                #pragma unroll
                for (int r = 0; r < 4; r++) acc[mt][q][r] = 0.f;

        #pragma unroll
        for (int ks = 0; ks < 8; ks++) {
            uint32_t ah[2][4], al[2][4];
            #pragma unroll
            for (int mb = 0; mb < 2; mb++) {
                uint32_t off = (uint32_t)((m0 + mb*16 + (lid & 15)) * PITCHB
                                          + (ks*16 + (lid >> 4) * 8) * 2);
                ldsm4(ah[mb], sb + SM_AH + off);
                ldsm4(al[mb], sb + SM_AL + off);
            }
            #pragma unroll
            for (int nb2 = 0; nb2 < 2; nb2++) {
                uint32_t boff = (uint32_t)(
                    (ks*16 + (lid & 7) + ((lid >> 3) & 1) * 8) * PITCHB
                    + (n0 + nb2*16 + (lid >> 4) * 8) * 2);
                uint32_t bh[4], bl[4];
                ldsm4t(bh, sb + SM_BH + boff);
                ldsm4t(bl, sb + SM_BL + boff);
                #pragma unroll
                for (int mt = 0; mt < 2; mt++) {
                    mma16816(acc[mt][2*nb2],   ah[mt], bh);
                    mma16816(acc[mt][2*nb2],   al[mt], bh);
                    mma16816(acc[mt][2*nb2],   ah[mt], bl);
                    mma16816(acc[mt][2*nb2+1], ah[mt], bh+2);
                    mma16816(acc[mt][2*nb2+1], al[mt], bh+2);
                    mma16816(acc[mt][2*nb2+1], ah[mt], bl+2);
                }
            }
        }

        // ---- epilogue: +bias, direct STG to scratch, register stats ----
        #pragma unroll
        for (int q = 0; q < 4; q++) {
            int c0 = n0 + (q >> 1) * 16 + (q & 1) * 8 + 2 * tig;
            float2 bb = *(const float2*)&sBias[c0];
            #pragma unroll
            for (int mt = 0; mt < 2; mt++) {
                int r = m0 + mt * 16 + gid;
                float2 v0 = make_float2(acc[mt][q][0] + bb.x, acc[mt][q][1] + bb.y);
                float2 v1 = make_float2(acc[mt][q][2] + bb.x, acc[mt][q][3] + bb.y);
                *(float2*)&g_h[(size_t)(e0 + r) * C + c0]     = v0;
                *(float2*)&g_h[(size_t)(e0 + r + 8) * C + c0] = v1;
                s1v[q].x += v0.x + v1.x;          s1v[q].y += v0.y + v1.y;
                s2v[q].x += v0.x*v0.x + v1.x*v1.x; s2v[q].y += v0.y*v0.y + v1.y*v1.y;
            }
        }
        __syncthreads();   // all ldsm of this A tile done before next overwrite
        buf ^= 1;
    }

    // ---- stats: reduce over gid (xor-shuffles), then shared, then global ----
    #pragma unroll
    for (int q = 0; q < 4; q++) {
        #pragma unroll
        for (int msk = 4; msk <= 16; msk <<= 1) {
            s1v[q].x += __shfl_xor_sync(0xffffffffu, s1v[q].x, msk);
            s1v[q].y += __shfl_xor_sync(0xffffffffu, s1v[q].y, msk);
            s2v[q].x += __shfl_xor_sync(0xffffffffu, s2v[q].x, msk);
            s2v[q].y += __shfl_xor_sync(0xffffffffu, s2v[q].y, msk);
        }
    }
    if (gid == 0) {
        #pragma unroll
        for (int q = 0; q < 4; q++) {
            int c0 = n0 + (q >> 1) * 16 + (q & 1) * 8 + 2 * tig;
            atomicAdd(&sRed1[c0], s1v[q].x);  atomicAdd(&sRed1[c0+1], s1v[q].y);
            atomicAdd(&sRed2[c0], s2v[q].x);  atomicAdd(&sRed2[c0+1], s2v[q].y);
        }
    }
    __syncthreads();
    if (tid < C) {
        atomicAdd((PASS == 1 ? g_sum1 : g_sum2) + tid, sRed1[tid]);
        atomicAdd((PASS == 1 ? g_sq1 : g_sq2) + tid, sRed2[tid]);
    }
}

__global__ void k_fin(const float* __restrict__ g, const float* __restrict__ be, int which) {
    int c = threadIdx.x;
    float sum = which ? g_sum2[c] : g_sum1[c];
    float sq  = which ? g_sq2[c]  : g_sq1[c];
    float mean = sum * (1.f / E_EDGES);
    float var  = sq * (1.f / E_EDGES) - mean * mean;
    float a = g[c] * rsqrtf(var + BN_EPS);
    float cc = be[c] - mean * a;
    if (which) { g_a2[c] = a; g_c2[c] = cc; }
    else       { g_a1[c] = a; g_c1[c] = cc; }
}

__global__ __launch_bounds__(256) void k_out(const float* __restrict__ wc,
                                             const float* __restrict__ bc,
                                             float* __restrict__ out)
{
    const int lane = threadIdx.x & 31;
    const int warp = threadIdx.x >> 5;
    const int nwarp = gridDim.x * 8;
    const int wg = blockIdx.x * 8 + warp;

    float4 a2 = *(const float4*)&g_a2[lane * 4];
    float4 c2 = *(const float4*)&g_c2[lane * 4];
    float4 wv = *(const float4*)&wc[lane * 4];
    float b = bc[0];

    for (size_t e = wg; e < E_EDGES; e += nwarp) {
        float4 v = *(const float4*)&g_h[e * C + lane * 4];
        float r = fmaxf(fmaf(v.x, a2.x, c2.x), 0.f) * wv.x
                + fmaxf(fmaf(v.y, a2.y, c2.y), 0.f) * wv.y
                + fmaxf(fmaf(v.z, a2.z, c2.z), 0.f) * wv.z
                + fmaxf(fmaf(v.w, a2.w, c2.w), 0.f) * wv.w;
        #pragma unroll
        for (int s = 16; s > 0; s >>= 1) r += __shfl_xor_sync(0xffffffffu, r, s);
        if (lane == 0) out[e] = r + b;
    }
}

extern "C" void kernel_launch(void* const* d_in, const int* in_sizes, int n_in,
                              void* d_out, int out_size) {
    const float* x     = (const float*)d_in[0];
    const void*  edges = d_in[1];
    const float* w1    = (const float*)d_in[2];
    const float* b1    = (const float*)d_in[3];
    const float* g1    = (const float*)d_in[4];
    const float* be1   = (const float*)d_in[5];
    const float* w2    = (const float*)d_in[6];
    const float* b2    = (const float*)d_in[7];
    const float* g2    = (const float*)d_in[8];
    const float* be2   = (const float*)d_in[9];
    const float* wc    = (const float*)d_in[10];
    const float* bc    = (const float*)d_in[11];
    float* out = (float*)d_out;
    (void)in_sizes; (void)n_in; (void)out_size;

    cudaFuncSetAttribute(k_pass_mma<1>, cudaFuncAttributeMaxDynamicSharedMemorySize, SM_TOTAL);
    cudaFuncSetAttribute(k_pass_mma<2>, cudaFuncAttributeMaxDynamicSharedMemorySize, SM_TOTAL);

    k_zero<<<1, 128>>>((const unsigned*)edges);
    k_pass_mma<1><<<296, 256, SM_TOTAL>>>(x, edges, w1, b1);
    k_fin<<<1, 128>>>(g1, be1, 0);
    k_pass_mma<2><<<296, 256, SM_TOTAL>>>(x, edges, w2, b2);
    k_fin<<<1, 128>>>(g2, be2, 1);
    k_out<<<2048, 256>>>(wc, bc, out);
}